// round 5
// baseline (speedup 1.0000x reference)
#include <cuda_runtime.h>

#define N_NODES 100000
#define DIM 64
#define EPW 128        // edges per warp in aggregation (E % EPW == 0 fast path)
#define P 66           // smem row pitch (floats)

// Scratch: aggY[i] = sum_{edges -> i} X[col].
// Zero-initialized at module load; gemm_kernel re-zeroes after consuming,
// so the "aggY == 0 on entry" invariant holds for every call/replay.
__device__ float g_aggY[(size_t)N_NODES * DIM];

// ---------------------------------------------------------------------------
// packed f32x2 helpers
// ---------------------------------------------------------------------------
__device__ __forceinline__ unsigned long long pack2(float lo, float hi) {
    unsigned long long r;
    asm("mov.b64 %0, {%1,%2};" : "=l"(r) : "f"(lo), "f"(hi));
    return r;
}
__device__ __forceinline__ unsigned long long fma2(unsigned long long a,
                                                   unsigned long long b,
                                                   unsigned long long c) {
    unsigned long long d;
    asm("fma.rn.f32x2 %0, %1, %2, %3;" : "=l"(d) : "l"(a), "l"(b), "l"(c));
    return d;
}
__device__ __forceinline__ float2 unpack2(unsigned long long p) {
    float lo, hi;
    asm("mov.b64 {%0,%1}, %2;" : "=f"(lo), "=f"(hi) : "l"(p));
    return make_float2(lo, hi);
}

// ---------------------------------------------------------------------------
// 1) edge aggregation: warp-segmented sum over sorted row_ids.
//    Lane owns 2 of 64 features. Fully unrolled 16 batches of 8 edges with
//    depth-2 prefetch: batch b+1's gathers are in flight while batch b is
//    accumulated. Flush via vector atomicAdd(float2*).
// ---------------------------------------------------------------------------
__global__ __launch_bounds__(256) void agg_kernel(const float* __restrict__ X,
                                                  const int* __restrict__ rows,
                                                  const int* __restrict__ cols,
                                                  int E) {
    const unsigned full = 0xffffffffu;
    const int warp = (blockIdx.x * blockDim.x + threadIdx.x) >> 5;
    const int lane = threadIdx.x & 31;
    const int base = warp * EPW;
    if (base >= E) return;

    const float2* __restrict__ Xp = (const float2*)X;

    float ax = 0.f, ay = 0.f;
    int cur = __ldg(rows + base);

    if (base + EPW <= E) {
        // ---- fast path: exactly 128 edges -------------------------------
        int rm[4], cm[4];
#pragma unroll
        for (int g = 0; g < 4; g++) {
            rm[g] = __ldg(rows + base + g * 32 + lane);
            cm[g] = __ldg(cols + base + g * 32 + lane);
        }

        float2 v[2][8];
        // prefetch batch 0
#pragma unroll
        for (int j = 0; j < 8; j++) {
            int ci = __shfl_sync(full, cm[0], j);
            v[0][j] = __ldg(Xp + (size_t)ci * 32 + lane);
        }

#pragma unroll
        for (int b = 0; b < 16; b++) {
            const int pb = b & 1, nb = pb ^ 1;
            if (b < 15) {
                const int g = (b + 1) >> 2, o = ((b + 1) & 3) * 8;
#pragma unroll
                for (int j = 0; j < 8; j++) {
                    int ci = __shfl_sync(full, cm[g], o + j);
                    v[nb][j] = __ldg(Xp + (size_t)ci * 32 + lane);
                }
            }
            const int g = b >> 2, o = (b & 3) * 8;
#pragma unroll
            for (int j = 0; j < 8; j++) {
                int ri = __shfl_sync(full, rm[g], o + j);
                if (ri != cur) {  // warp-uniform
                    float2* dst = (float2*)(g_aggY + (size_t)cur * DIM) + lane;
                    atomicAdd(dst, make_float2(ax, ay));
                    ax = 0.f; ay = 0.f;
                    cur = ri;
                }
                ax += v[pb][j].x;
                ay += v[pb][j].y;
            }
        }
    } else {
        // ---- generic tail path ------------------------------------------
        int end = E;
        for (int e0 = base; e0 < end; e0 += 32) {
            int n = min(32, end - e0);
            int r = 0, c = 0;
            if (lane < n) {
                r = __ldg(rows + e0 + lane);
                c = __ldg(cols + e0 + lane);
            }
            for (int i = 0; i < n; i++) {
                int ri = __shfl_sync(full, r, i);
                int ci = __shfl_sync(full, c, i);
                if (ri != cur) {
                    float2* dst = (float2*)(g_aggY + (size_t)cur * DIM) + lane;
                    atomicAdd(dst, make_float2(ax, ay));
                    ax = 0.f; ay = 0.f;
                    cur = ri;
                }
                float2 v = __ldg(Xp + (size_t)ci * 32 + lane);
                ax += v.x;
                ay += v.y;
            }
        }
    }
    float2* dst = (float2*)(g_aggY + (size_t)cur * DIM) + lane;
    atomicAdd(dst, make_float2(ax, ay));
}

// ---------------------------------------------------------------------------
// 2) fused dual GEMM: out = (aggY/dd1) @ W + X @ W1, then re-zero aggY.
//    64 rows/block, 256 threads, 4x4 thread tile, k-paired f32x2 FMA.
// ---------------------------------------------------------------------------
__global__ __launch_bounds__(256) void gemm_kernel(const float* __restrict__ X,
                                                   const float* __restrict__ W,
                                                   const float* __restrict__ W1,
                                                   const float* __restrict__ dd1,
                                                   float* __restrict__ out,
                                                   int N) {
    extern __shared__ float smem[];
    float* Xs  = smem;                  // [64][P]
    float* Ys  = Xs + 64 * P;           // [64][P]
    float* Ws  = Ys + 64 * P;           // [64*64]
    float* W1s = Ws + DIM * DIM;        // [64*64]

    const int tid  = threadIdx.x;
    const int row0 = blockIdx.x * 64;

    for (int i = tid; i < (DIM * DIM) / 4; i += 256) {
        ((float4*)Ws)[i]  = __ldg((const float4*)W + i);
        ((float4*)W1s)[i] = __ldg((const float4*)W1 + i);
    }

    const float4 z4 = make_float4(0.f, 0.f, 0.f, 0.f);
    for (int idx = tid; idx < 64 * 16; idx += 256) {
        int r   = idx >> 4;
        int k4  = (idx & 15) * 4;
        int row = row0 + r;
        float4 v = z4, u = z4;
        if (row < N) {
            v = __ldg((const float4*)(X + (size_t)row * DIM + k4));
            float4* ap = (float4*)(g_aggY + (size_t)row * DIM + k4);
            u = *ap;
            *ap = z4;                       // re-zero for the next call/replay
            float inv = __frcp_rn(__ldg(dd1 + row));
            u.x *= inv; u.y *= inv; u.z *= inv; u.w *= inv;
        }
        float* xr = Xs + r * P + k4;
        xr[0] = v.x; xr[1] = v.y; xr[2] = v.z; xr[3] = v.w;
        float* yr = Ys + r * P + k4;
        yr[0] = u.x; yr[1] = u.y; yr[2] = u.z; yr[3] = u.w;
    }
    __syncthreads();

    const int cq = tid & 15;
    const int rq = tid >> 4;
    const int c0 = cq * 4;
    const int rt = rq * 4;

    unsigned long long acc[4][4];
#pragma unroll
    for (int i = 0; i < 4; i++)
#pragma unroll
        for (int j = 0; j < 4; j++) acc[i][j] = 0ull;

#pragma unroll 4
    for (int k = 0; k < DIM; k += 2) {
        float4 wa = *(const float4*)(Ws  + k * DIM + c0);
        float4 wb = *(const float4*)(Ws  + (k + 1) * DIM + c0);
        float4 qa = *(const float4*)(W1s + k * DIM + c0);
        float4 qb = *(const float4*)(W1s + (k + 1) * DIM + c0);
        unsigned long long wp0 = pack2(wa.x, wb.x);
        unsigned long long wp1 = pack2(wa.y, wb.y);
        unsigned long long wp2 = pack2(wa.z, wb.z);
        unsigned long long wp3 = pack2(wa.w, wb.w);
        unsigned long long qp0 = pack2(qa.x, qb.x);
        unsigned long long qp1 = pack2(qa.y, qb.y);
        unsigned long long qp2 = pack2(qa.z, qb.z);
        unsigned long long qp3 = pack2(qa.w, qb.w);
#pragma unroll
        for (int i = 0; i < 4; i++) {
            float2 xv = *(const float2*)(Xs + (rt + i) * P + k);
            float2 yv = *(const float2*)(Ys + (rt + i) * P + k);
            unsigned long long xp = pack2(xv.x, xv.y);
            unsigned long long yp = pack2(yv.x, yv.y);
            acc[i][0] = fma2(yp, wp0, acc[i][0]);
            acc[i][1] = fma2(yp, wp1, acc[i][1]);
            acc[i][2] = fma2(yp, wp2, acc[i][2]);
            acc[i][3] = fma2(yp, wp3, acc[i][3]);
            acc[i][0] = fma2(xp, qp0, acc[i][0]);
            acc[i][1] = fma2(xp, qp1, acc[i][1]);
            acc[i][2] = fma2(xp, qp2, acc[i][2]);
            acc[i][3] = fma2(xp, qp3, acc[i][3]);
        }
    }

#pragma unroll
    for (int i = 0; i < 4; i++) {
        int row = row0 + rt + i;
        if (row < N) {
            float2 a0 = unpack2(acc[i][0]);
            float2 a1 = unpack2(acc[i][1]);
            float2 a2 = unpack2(acc[i][2]);
            float2 a3 = unpack2(acc[i][3]);
            *(float4*)(out + (size_t)row * DIM + c0) =
                make_float4(a0.x + a0.y, a1.x + a1.y, a2.x + a2.y, a3.x + a3.y);
        }
    }
}

// ---------------------------------------------------------------------------
extern "C" void kernel_launch(void* const* d_in, const int* in_sizes, int n_in,
                              void* d_out, int out_size) {
    const float* X    = (const float*)d_in[0];   // [N, 64]
    const float* W    = (const float*)d_in[1];   // [64, 64]
    const float* W1   = (const float*)d_in[2];   // [64, 64]
    const float* dd1  = (const float*)d_in[3];   // [N, 1]
    const int*   rows = (const int*)d_in[4];     // [E] sorted
    const int*   cols = (const int*)d_in[5];     // [E]
    float*       out  = (float*)d_out;           // [N, 64]

    int N = in_sizes[0] / DIM;
    int E = in_sizes[4];

    // 1) edge aggregation into g_aggY (assumed zero on entry; see gemm)
    {
        int nwarps  = (E + EPW - 1) / EPW;
        int nblocks = (nwarps + 7) / 8;
        agg_kernel<<<nblocks, 256>>>(X, rows, cols, E);
    }

    // 2) dual GEMM -> out (+ re-zero g_aggY)
    {
        int nblocks = (N + 63) / 64;
        size_t smem_bytes = (2 * 64 * P + 2 * 64 * 64) * sizeof(float);
        static int smem_set = 0;
        if (!smem_set) {
            cudaFuncSetAttribute(gemm_kernel,
                                 cudaFuncAttributeMaxDynamicSharedMemorySize,
                                 (int)smem_bytes);
            smem_set = 1;
        }
        gemm_kernel<<<nblocks, 256, smem_bytes>>>(X, W, W1, dd1, out, N);
    }
}

// round 7
// speedup vs baseline: 1.1387x; 1.1387x over previous
#include <cuda_runtime.h>

#define N_NODES 100000
#define DIM 64
#define EPW 128        // edges per warp in aggregation
#define P 66           // smem slab row pitch (floats), even -> 8B-aligned pairs

// Scratch: aggY[i] = sum_{edges -> i} X[col].
// Zero-initialized at module load; gemm_kernel re-zeroes its slab at the END
// of each call, so "aggY == 0 on entry" holds for every call/replay.
__device__ float g_aggY[(size_t)N_NODES * DIM];

// ---------------------------------------------------------------------------
__device__ __forceinline__ unsigned long long fma2(unsigned long long a,
                                                   unsigned long long b,
                                                   unsigned long long c) {
    unsigned long long d;
    asm("fma.rn.f32x2 %0, %1, %2, %3;" : "=l"(d) : "l"(a), "l"(b), "l"(c));
    return d;
}
__device__ __forceinline__ float2 unpack2(unsigned long long p) {
    float lo, hi;
    asm("mov.b64 {%0,%1}, %2;" : "=f"(lo), "=f"(hi) : "l"(p));
    return make_float2(lo, hi);
}

// ---------------------------------------------------------------------------
// 1) edge aggregation: warp-segmented sum over sorted row_ids.
//    Lane owns 2 of 64 features; depth-2 prefetch of 8-edge batches.
// ---------------------------------------------------------------------------
__global__ __launch_bounds__(256) void agg_kernel(const float* __restrict__ X,
                                                  const int* __restrict__ rows,
                                                  const int* __restrict__ cols,
                                                  int E) {
    const unsigned full = 0xffffffffu;
    const int warp = (blockIdx.x * blockDim.x + threadIdx.x) >> 5;
    const int lane = threadIdx.x & 31;
    const int base = warp * EPW;
    if (base >= E) return;

    const float2* __restrict__ Xp = (const float2*)X;

    float ax = 0.f, ay = 0.f;
    int cur = __ldg(rows + base);

    if (base + EPW <= E) {
        int rm[4], cm[4];
#pragma unroll
        for (int g = 0; g < 4; g++) {
            rm[g] = __ldg(rows + base + g * 32 + lane);
            cm[g] = __ldg(cols + base + g * 32 + lane);
        }

        float2 v[2][8];
#pragma unroll
        for (int j = 0; j < 8; j++) {
            int ci = __shfl_sync(full, cm[0], j);
            v[0][j] = __ldg(Xp + (size_t)ci * 32 + lane);
        }

#pragma unroll
        for (int b = 0; b < 16; b++) {
            const int pb = b & 1, nb = pb ^ 1;
            if (b < 15) {
                const int g = (b + 1) >> 2, o = ((b + 1) & 3) * 8;
#pragma unroll
                for (int j = 0; j < 8; j++) {
                    int ci = __shfl_sync(full, cm[g], o + j);
                    v[nb][j] = __ldg(Xp + (size_t)ci * 32 + lane);
                }
            }
            const int g = b >> 2, o = (b & 3) * 8;
#pragma unroll
            for (int j = 0; j < 8; j++) {
                int ri = __shfl_sync(full, rm[g], o + j);
                if (ri != cur) {  // warp-uniform
                    float2* dst = (float2*)(g_aggY + (size_t)cur * DIM) + lane;
                    atomicAdd(dst, make_float2(ax, ay));
                    ax = 0.f; ay = 0.f;
                    cur = ri;
                }
                ax += v[pb][j].x;
                ay += v[pb][j].y;
            }
        }
    } else {
        int end = E;
        for (int e0 = base; e0 < end; e0 += 32) {
            int n = min(32, end - e0);
            int r = 0, c = 0;
            if (lane < n) {
                r = __ldg(rows + e0 + lane);
                c = __ldg(cols + e0 + lane);
            }
            for (int i = 0; i < n; i++) {
                int ri = __shfl_sync(full, r, i);
                int ci = __shfl_sync(full, c, i);
                if (ri != cur) {
                    float2* dst = (float2*)(g_aggY + (size_t)cur * DIM) + lane;
                    atomicAdd(dst, make_float2(ax, ay));
                    ax = 0.f; ay = 0.f;
                    cur = ri;
                }
                float2 v = __ldg(Xp + (size_t)ci * 32 + lane);
                ax += v.x;
                ay += v.y;
            }
        }
    }
    float2* dst = (float2*)(g_aggY + (size_t)cur * DIM) + lane;
    atomicAdd(dst, make_float2(ax, ay));
}

// ---------------------------------------------------------------------------
// 2) dual GEMM: out = (aggY/dd1) @ W + X @ W1, then re-zero aggY slab (end).
//    64 rows/block, 256 threads, 4x4 tile, k-pair FFMA2, pre-packed weights:
//    Wp[kp][c] = (W[2kp][c], W[2kp+1][c]) so the inner loop has NO packing.
// ---------------------------------------------------------------------------
__global__ __launch_bounds__(256) void gemm_kernel(const float* __restrict__ X,
                                                   const float* __restrict__ W,
                                                   const float* __restrict__ W1,
                                                   const float* __restrict__ dd1,
                                                   float* __restrict__ out,
                                                   int N) {
    extern __shared__ float smem[];
    float* Xs = smem;                   // [64][P]
    float* Ys = Xs + 64 * P;            // [64][P]
    float* Wp = Ys + 64 * P;            // packed [32][64] float2 = 4096 floats
    float* Qp = Wp + 2 * 32 * DIM;      // packed W1, same layout

    const int tid  = threadIdx.x;
    const int row0 = blockIdx.x * 64;

    // ---- load + pack weights: Wp[kp*128 + 2*c + (k&1)] = W[k*64 + c] ------
    for (int i = tid; i < (DIM * DIM) / 4; i += 256) {
        int k  = i >> 4;             // row 0..63
        int c4 = (i & 15) * 4;       // col 0,4,...,60
        float4 w  = __ldg((const float4*)W + i);
        float4 q  = __ldg((const float4*)W1 + i);
        float* wd = Wp + (k >> 1) * 128 + (k & 1);
        float* qd = Qp + (k >> 1) * 128 + (k & 1);
        wd[2 * (c4 + 0)] = w.x; wd[2 * (c4 + 1)] = w.y;
        wd[2 * (c4 + 2)] = w.z; wd[2 * (c4 + 3)] = w.w;
        qd[2 * (c4 + 0)] = q.x; qd[2 * (c4 + 1)] = q.y;
        qd[2 * (c4 + 2)] = q.z; qd[2 * (c4 + 3)] = q.w;
    }

    // ---- load slabs (pure __ldg, no stores) -------------------------------
    const float4 z4 = make_float4(0.f, 0.f, 0.f, 0.f);
    for (int idx = tid; idx < 64 * 16; idx += 256) {
        int r   = idx >> 4;
        int k4  = (idx & 15) * 4;
        int row = row0 + r;
        float4 v = z4, u = z4;
        if (row < N) {
            v = __ldg((const float4*)(X + (size_t)row * DIM + k4));
            u = __ldg((const float4*)(g_aggY + (size_t)row * DIM + k4));
            float inv = __frcp_rn(__ldg(dd1 + row));
            u.x *= inv; u.y *= inv; u.z *= inv; u.w *= inv;
        }
        float* xr = Xs + r * P + k4;
        xr[0] = v.x; xr[1] = v.y; xr[2] = v.z; xr[3] = v.w;
        float* yr = Ys + r * P + k4;
        yr[0] = u.x; yr[1] = u.y; yr[2] = u.z; yr[3] = u.w;
    }
    __syncthreads();

    const int cq = tid & 15;
    const int rq = tid >> 4;
    const int c0 = cq * 4;
    const int rt = rq * 4;

    unsigned long long acc[4][4];
#pragma unroll
    for (int i = 0; i < 4; i++)
#pragma unroll
        for (int j = 0; j < 4; j++) acc[i][j] = 0ull;

    const unsigned long long* Wq = (const unsigned long long*)Wp + c0;
    const unsigned long long* Q2 = (const unsigned long long*)Qp + c0;

#pragma unroll 8
    for (int kp = 0; kp < 32; kp++) {
        unsigned long long w0 = Wq[kp * 64 + 0];
        unsigned long long w1 = Wq[kp * 64 + 1];
        unsigned long long w2 = Wq[kp * 64 + 2];
        unsigned long long w3 = Wq[kp * 64 + 3];
        unsigned long long q0 = Q2[kp * 64 + 0];
        unsigned long long q1 = Q2[kp * 64 + 1];
        unsigned long long q2 = Q2[kp * 64 + 2];
        unsigned long long q3 = Q2[kp * 64 + 3];
#pragma unroll
        for (int i = 0; i < 4; i++) {
            unsigned long long xp =
                *(const unsigned long long*)(Xs + (rt + i) * P + 2 * kp);
            unsigned long long yp =
                *(const unsigned long long*)(Ys + (rt + i) * P + 2 * kp);
            acc[i][0] = fma2(yp, w0, acc[i][0]);
            acc[i][1] = fma2(yp, w1, acc[i][1]);
            acc[i][2] = fma2(yp, w2, acc[i][2]);
            acc[i][3] = fma2(yp, w3, acc[i][3]);
            acc[i][0] = fma2(xp, q0, acc[i][0]);
            acc[i][1] = fma2(xp, q1, acc[i][1]);
            acc[i][2] = fma2(xp, q2, acc[i][2]);
            acc[i][3] = fma2(xp, q3, acc[i][3]);
        }
    }

#pragma unroll
    for (int i = 0; i < 4; i++) {
        int row = row0 + rt + i;
        if (row < N) {
            float2 a0 = unpack2(acc[i][0]);
            float2 a1 = unpack2(acc[i][1]);
            float2 a2 = unpack2(acc[i][2]);
            float2 a3 = unpack2(acc[i][3]);
            *(float4*)(out + (size_t)row * DIM + c0) =
                make_float4(a0.x + a0.y, a1.x + a1.y, a2.x + a2.y, a3.x + a3.y);
        }
    }

    // ---- re-zero our aggY slab for the next call/replay (independent) -----
    for (int idx = tid; idx < 64 * 16; idx += 256) {
        int row = row0 + (idx >> 4);
        if (row < N) {
            ((float4*)(g_aggY + (size_t)row * DIM))[idx & 15] = z4;
        }
    }
}

// ---------------------------------------------------------------------------
extern "C" void kernel_launch(void* const* d_in, const int* in_sizes, int n_in,
                              void* d_out, int out_size) {
    const float* X    = (const float*)d_in[0];   // [N, 64]
    const float* W    = (const float*)d_in[1];   // [64, 64]
    const float* W1   = (const float*)d_in[2];   // [64, 64]
    const float* dd1  = (const float*)d_in[3];   // [N, 1]
    const int*   rows = (const int*)d_in[4];     // [E] sorted
    const int*   cols = (const int*)d_in[5];     // [E]
    float*       out  = (float*)d_out;           // [N, 64]

    int N = in_sizes[0] / DIM;
    int E = in_sizes[4];

    // 1) edge aggregation into g_aggY (zero on entry; see gemm epilogue)
    {
        int nwarps  = (E + EPW - 1) / EPW;
        int nblocks = (nwarps + 7) / 8;
        agg_kernel<<<nblocks, 256>>>(X, rows, cols, E);
    }

    // 2) dual GEMM -> out (+ re-zero g_aggY at end)
    {
        int nblocks = (N + 63) / 64;
        size_t smem_bytes = (2 * 64 * P + 2 * 2 * 32 * DIM) * sizeof(float);
        static int smem_set = 0;
        if (!smem_set) {
            cudaFuncSetAttribute(gemm_kernel,
                                 cudaFuncAttributeMaxDynamicSharedMemorySize,
                                 (int)smem_bytes);
            smem_set = 1;
        }
        gemm_kernel<<<nblocks, 256, smem_bytes>>>(X, W, W1, dd1, out, N);
    }
}

// round 11
// speedup vs baseline: 1.4724x; 1.2930x over previous
#include <cuda_runtime.h>

#define N_NODES 100000
#define DIM 64
#define EPW 128        // edges per warp in aggregation
#define P 66           // smem slab row pitch (floats), even -> 8B-aligned pairs

// Scratch: aggY[i] = sum_{edges -> i} X[col].
// Zero-initialized at module load; gemm_kernel re-zeroes its slab at the END
// of each call, so "aggY == 0 on entry" holds for every call/replay.
__device__ float g_aggY[(size_t)N_NODES * DIM];

// ---------------------------------------------------------------------------
__device__ __forceinline__ unsigned long long fma2(unsigned long long a,
                                                   unsigned long long b,
                                                   unsigned long long c) {
    unsigned long long d;
    asm("fma.rn.f32x2 %0, %1, %2, %3;" : "=l"(d) : "l"(a), "l"(b), "l"(c));
    return d;
}
__device__ __forceinline__ float2 unpack2(unsigned long long p) {
    float lo, hi;
    asm("mov.b64 {%0,%1}, %2;" : "=f"(lo), "=f"(hi) : "l"(p));
    return make_float2(lo, hi);
}

// ---------------------------------------------------------------------------
// 1) edge aggregation: warp-segmented sum over sorted row_ids.
//    Lane owns 2 of 64 features; depth-2 prefetch of 8-edge batches.
// ---------------------------------------------------------------------------
__global__ __launch_bounds__(256) void agg_kernel(const float* __restrict__ X,
                                                  const int* __restrict__ rows,
                                                  const int* __restrict__ cols,
                                                  int E) {
    const unsigned full = 0xffffffffu;
    const int warp = (blockIdx.x * blockDim.x + threadIdx.x) >> 5;
    const int lane = threadIdx.x & 31;
    const int base = warp * EPW;
    if (base >= E) return;

    const float2* __restrict__ Xp = (const float2*)X;

    float ax = 0.f, ay = 0.f;
    int cur = __ldg(rows + base);

    if (base + EPW <= E) {
        int rm[4], cm[4];
#pragma unroll
        for (int g = 0; g < 4; g++) {
            rm[g] = __ldg(rows + base + g * 32 + lane);
            cm[g] = __ldg(cols + base + g * 32 + lane);
        }

        float2 v[2][8];
#pragma unroll
        for (int j = 0; j < 8; j++) {
            int ci = __shfl_sync(full, cm[0], j);
            v[0][j] = __ldg(Xp + (size_t)ci * 32 + lane);
        }

#pragma unroll
        for (int b = 0; b < 16; b++) {
            const int pb = b & 1, nb = pb ^ 1;
            if (b < 15) {
                const int g = (b + 1) >> 2, o = ((b + 1) & 3) * 8;
#pragma unroll
                for (int j = 0; j < 8; j++) {
                    int ci = __shfl_sync(full, cm[g], o + j);
                    v[nb][j] = __ldg(Xp + (size_t)ci * 32 + lane);
                }
            }
            const int g = b >> 2, o = (b & 3) * 8;
#pragma unroll
            for (int j = 0; j < 8; j++) {
                int ri = __shfl_sync(full, rm[g], o + j);
                if (ri != cur) {  // warp-uniform
                    float2* dst = (float2*)(g_aggY + (size_t)cur * DIM) + lane;
                    atomicAdd(dst, make_float2(ax, ay));
                    ax = 0.f; ay = 0.f;
                    cur = ri;
                }
                ax += v[pb][j].x;
                ay += v[pb][j].y;
            }
        }
    } else {
        int end = E;
        for (int e0 = base; e0 < end; e0 += 32) {
            int n = min(32, end - e0);
            int r = 0, c = 0;
            if (lane < n) {
                r = __ldg(rows + e0 + lane);
                c = __ldg(cols + e0 + lane);
            }
            for (int i = 0; i < n; i++) {
                int ri = __shfl_sync(full, r, i);
                int ci = __shfl_sync(full, c, i);
                if (ri != cur) {
                    float2* dst = (float2*)(g_aggY + (size_t)cur * DIM) + lane;
                    atomicAdd(dst, make_float2(ax, ay));
                    ax = 0.f; ay = 0.f;
                    cur = ri;
                }
                float2 v = __ldg(Xp + (size_t)ci * 32 + lane);
                ax += v.x;
                ay += v.y;
            }
        }
    }
    float2* dst = (float2*)(g_aggY + (size_t)cur * DIM) + lane;
    atomicAdd(dst, make_float2(ax, ay));
}

// ---------------------------------------------------------------------------
// 2) dual GEMM: out = (aggY/dd1) @ W + X @ W1, then re-zero aggY slab (end).
//    64 rows/block, 256 threads, 4x4 tile, k-pair FFMA2.
//    Weights pre-packed CONFLICT-FREE:
//      Wg[(kp*4+jj)*16 + cq] (ull) = (W[2kp][4cq+jj], W[2kp+1][4cq+jj])
//    so each (kp,jj) warp load touches 16 consecutive ulls = 128B, 1 cycle.
// ---------------------------------------------------------------------------
__global__ __launch_bounds__(256) void gemm_kernel(const float* __restrict__ X,
                                                   const float* __restrict__ W,
                                                   const float* __restrict__ W1,
                                                   const float* __restrict__ dd1,
                                                   float* __restrict__ out,
                                                   int N) {
    extern __shared__ float smem[];
    float* Xs = smem;                   // [64][P]
    float* Ys = Xs + 64 * P;            // [64][P]
    float* Wg = Ys + 64 * P;            // packed 2048 ull = 4096 floats
    float* Qg = Wg + 2 * 32 * DIM;      // packed W1, same layout

    const int tid  = threadIdx.x;
    const int row0 = blockIdx.x * 64;

    // ---- load + pack weights (conflict-free target layout) ----------------
    // thread i loads W row k = i>>4, cols c4..c4+3 with c4 = (i&15)*4.
    // scatter: float index = 2*((kp*4 + jj)*16 + q) + (k&1), q = i&15.
    for (int i = tid; i < (DIM * DIM) / 4; i += 256) {
        int k   = i >> 4;
        int q   = i & 15;
        int kp  = k >> 1;
        int par = k & 1;
        float4 w = __ldg((const float4*)W + i);
        float4 u = __ldg((const float4*)W1 + i);
        int b0 = 2 * (kp * 64 + q) + par;   // jj=0; jj step = 32 floats
        Wg[b0 + 0]  = w.x; Wg[b0 + 32] = w.y;
        Wg[b0 + 64] = w.z; Wg[b0 + 96] = w.w;
        Qg[b0 + 0]  = u.x; Qg[b0 + 32] = u.y;
        Qg[b0 + 64] = u.z; Qg[b0 + 96] = u.w;
    }

    // ---- load slabs (pure __ldg, no stores) -------------------------------
    const float4 z4 = make_float4(0.f, 0.f, 0.f, 0.f);
    for (int idx = tid; idx < 64 * 16; idx += 256) {
        int r   = idx >> 4;
        int k4  = (idx & 15) * 4;
        int row = row0 + r;
        float4 v = z4, u = z4;
        if (row < N) {
            v = __ldg((const float4*)(X + (size_t)row * DIM + k4));
            u = __ldg((const float4*)(g_aggY + (size_t)row * DIM + k4));
            float inv = __frcp_rn(__ldg(dd1 + row));
            u.x *= inv; u.y *= inv; u.z *= inv; u.w *= inv;
        }
        float* xr = Xs + r * P + k4;
        xr[0] = v.x; xr[1] = v.y; xr[2] = v.z; xr[3] = v.w;
        float* yr = Ys + r * P + k4;
        yr[0] = u.x; yr[1] = u.y; yr[2] = u.z; yr[3] = u.w;
    }
    __syncthreads();

    const int cq = tid & 15;
    const int rq = tid >> 4;
    const int rt = rq * 4;
    const int c0 = cq * 4;

    unsigned long long acc[4][4];
#pragma unroll
    for (int i = 0; i < 4; i++)
#pragma unroll
        for (int j = 0; j < 4; j++) acc[i][j] = 0ull;

    const unsigned long long* Wq = (const unsigned long long*)Wg + cq;
    const unsigned long long* Qq = (const unsigned long long*)Qg + cq;

#pragma unroll 8
    for (int kp = 0; kp < 32; kp++) {
        unsigned long long w0 = Wq[(kp * 4 + 0) * 16];
        unsigned long long w1 = Wq[(kp * 4 + 1) * 16];
        unsigned long long w2 = Wq[(kp * 4 + 2) * 16];
        unsigned long long w3 = Wq[(kp * 4 + 3) * 16];
        unsigned long long q0 = Qq[(kp * 4 + 0) * 16];
        unsigned long long q1 = Qq[(kp * 4 + 1) * 16];
        unsigned long long q2 = Qq[(kp * 4 + 2) * 16];
        unsigned long long q3 = Qq[(kp * 4 + 3) * 16];
#pragma unroll
        for (int i = 0; i < 4; i++) {
            unsigned long long xp =
                *(const unsigned long long*)(Xs + (rt + i) * P + 2 * kp);
            unsigned long long yp =
                *(const unsigned long long*)(Ys + (rt + i) * P + 2 * kp);
            acc[i][0] = fma2(yp, w0, acc[i][0]);
            acc[i][1] = fma2(yp, w1, acc[i][1]);
            acc[i][2] = fma2(yp, w2, acc[i][2]);
            acc[i][3] = fma2(yp, w3, acc[i][3]);
            acc[i][0] = fma2(xp, q0, acc[i][0]);
            acc[i][1] = fma2(xp, q1, acc[i][1]);
            acc[i][2] = fma2(xp, q2, acc[i][2]);
            acc[i][3] = fma2(xp, q3, acc[i][3]);
        }
    }

#pragma unroll
    for (int i = 0; i < 4; i++) {
        int row = row0 + rt + i;
        if (row < N) {
            float2 a0 = unpack2(acc[i][0]);
            float2 a1 = unpack2(acc[i][1]);
            float2 a2 = unpack2(acc[i][2]);
            float2 a3 = unpack2(acc[i][3]);
            *(float4*)(out + (size_t)row * DIM + c0) =
                make_float4(a0.x + a0.y, a1.x + a1.y, a2.x + a2.y, a3.x + a3.y);
        }
    }

    // ---- re-zero our aggY slab for the next call/replay -------------------
    for (int idx = tid; idx < 64 * 16; idx += 256) {
        int row = row0 + (idx >> 4);
        if (row < N) {
            ((float4*)(g_aggY + (size_t)row * DIM))[idx & 15] = z4;
        }
    }
}

// ---------------------------------------------------------------------------
extern "C" void kernel_launch(void* const* d_in, const int* in_sizes, int n_in,
                              void* d_out, int out_size) {
    const float* X    = (const float*)d_in[0];   // [N, 64]
    const float* W    = (const float*)d_in[1];   // [64, 64]
    const float* W1   = (const float*)d_in[2];   // [64, 64]
    const float* dd1  = (const float*)d_in[3];   // [N, 1]
    const int*   rows = (const int*)d_in[4];     // [E] sorted
    const int*   cols = (const int*)d_in[5];     // [E]
    float*       out  = (float*)d_out;           // [N, 64]

    int N = in_sizes[0] / DIM;
    int E = in_sizes[4];

    // 1) edge aggregation into g_aggY (zero on entry; see gemm epilogue)
    {
        int nwarps  = (E + EPW - 1) / EPW;
        int nblocks = (nwarps + 7) / 8;
        agg_kernel<<<nblocks, 256>>>(X, rows, cols, E);
    }

    // 2) dual GEMM -> out (+ re-zero g_aggY at end)
    {
        int nblocks = (N + 63) / 64;
        size_t smem_bytes = (2 * 64 * P + 2 * 2 * 32 * DIM) * sizeof(float);
        static int smem_set = 0;
        if (!smem_set) {
            cudaFuncSetAttribute(gemm_kernel,
                                 cudaFuncAttributeMaxDynamicSharedMemorySize,
                                 (int)smem_bytes);
            smem_set = 1;
        }
        gemm_kernel<<<nblocks, 256, smem_bytes>>>(X, W, W1, dd1, out, N);
    }
}